// round 6
// baseline (speedup 1.0000x reference)
#include <cuda_runtime.h>
#include <cstdint>

// out[m,n] = a * (h[m,:] @ B2[:,n]) + (1-a) * h[m,n]
// B2[k, head*64+d] = W[head,k,d]; a = clip(res_alpha,0,1).
// (softmax row-sums are exactly 1 -> attention block is identity; adj unused)
//
// mma.sync.m16n8k8 tf32 with 3xTF32 split (fp32-grade accuracy):
//   x = hi + lo, hi = x & 0xFFFFE000;  D = Ahi*Bhi + Ahi*Blo + Alo*Bhi
// R4: cp.async double-buffered smem + term-major MMA issue order
// (acc-reuse distance 8) to unstall the tensor pipe.

#define K_DIM   256
#define NDIM    256
#define BM      128
#define BN      128
#define KC      32
#define NCHUNK  (K_DIM / KC)
#define LDS_    36            // smem row stride in floats
#define STAGEF  ((BM + BN) * LDS_)   // floats per stage = 9216
#define THREADS 256
#define HIMASK  0xFFFFE000u

__device__ float g_Bt[NDIM * K_DIM];   // W transposed: [n][k]

__global__ void prep_Bt(const float* __restrict__ W) {
    int idx = blockIdx.x * blockDim.x + threadIdx.x;   // 65536
    int k = idx >> 8;
    int n = idx & 255;
    int head = n >> 6, d = n & 63;
    g_Bt[n * K_DIM + k] = W[((size_t)head * K_DIM + k) * 64 + d];
}

__device__ __forceinline__ void mma_tf32(float d[4],
                                         const uint32_t a[4],
                                         uint32_t b0, uint32_t b1) {
    asm volatile(
        "mma.sync.aligned.m16n8k8.row.col.f32.tf32.tf32.f32 "
        "{%0,%1,%2,%3}, {%4,%5,%6,%7}, {%8,%9}, {%0,%1,%2,%3};"
        : "+f"(d[0]), "+f"(d[1]), "+f"(d[2]), "+f"(d[3])
        : "r"(a[0]), "r"(a[1]), "r"(a[2]), "r"(a[3]), "r"(b0), "r"(b1));
}

__device__ __forceinline__ void cp16(uint32_t saddr, const float* g) {
    asm volatile("cp.async.cg.shared.global [%0], [%1], 16;"
                 :: "r"(saddr), "l"(g) : "memory");
}

__global__ __launch_bounds__(THREADS, 2)
void gat_mma_gemm(const float* __restrict__ h,
                  const float* __restrict__ res_alpha,
                  float* __restrict__ out)
{
    extern __shared__ float smem[];

    const int tid = threadIdx.x;
    const int wid = tid >> 5;
    const int lid = tid & 31;
    const int grp = lid >> 2;          // 0..7
    const int tig = lid & 3;           // 0..3

    const int m0 = blockIdx.y * BM;
    const int n0 = blockIdx.x * BN;
    const int wm = (wid & 3) * 32;     // warp M offset
    const int wn = (wid >> 2) * 64;    // warp N offset

    const uint32_t smem_b = (uint32_t)__cvta_generic_to_shared(smem);

    // per-thread cp.async target offsets (row/col fixed across chunks)
    const int fid_row = tid >> 3;            // 0..31 base row per j-step of 32
    const int fid_kq  = (tid & 7) << 2;

    float acc[2][8][4];
    #pragma unroll
    for (int mt = 0; mt < 2; ++mt)
        #pragma unroll
        for (int nt = 0; nt < 8; ++nt)
            #pragma unroll
            for (int q = 0; q < 4; ++q)
                acc[mt][nt][q] = 0.0f;

    // ---- async load of one chunk into stage s ----
    auto load_chunk = [&](int c, int s) {
        const int k0 = c * KC;
        const uint32_t sa = smem_b + (uint32_t)(s * STAGEF) * 4u;
        const uint32_t sbb = sa + (uint32_t)(BM * LDS_) * 4u;
        #pragma unroll
        for (int j = 0; j < 4; ++j) {
            int row = fid_row + j * 32;
            cp16(sa + (uint32_t)(row * LDS_ + fid_kq) * 4u,
                 &h[(size_t)(m0 + row) * K_DIM + k0 + fid_kq]);
            cp16(sbb + (uint32_t)(row * LDS_ + fid_kq) * 4u,
                 &g_Bt[(size_t)(n0 + row) * K_DIM + k0 + fid_kq]);
        }
        asm volatile("cp.async.commit_group;" ::: "memory");
    };

    load_chunk(0, 0);

    for (int c = 0; c < NCHUNK; ++c) {
        const int s = c & 1;
        if (c + 1 < NCHUNK) {
            load_chunk(c + 1, (c + 1) & 1);
            asm volatile("cp.async.wait_group 1;" ::: "memory");
        } else {
            asm volatile("cp.async.wait_group 0;" ::: "memory");
        }
        __syncthreads();

        const float* As = smem + s * STAGEF;
        const float* Bs = As + BM * LDS_;

        #pragma unroll
        for (int k8 = 0; k8 < KC / 8; ++k8) {
            const int kb = k8 * 8;

            // ---- A fragments for both M tiles, split hi/lo ----
            uint32_t ah[2][4], al[2][4];
            #pragma unroll
            for (int mt = 0; mt < 2; ++mt) {
                const int ab = (wm + mt * 16 + grp) * LDS_ + kb + tig;
                float f0 = As[ab];
                float f1 = As[ab + 8 * LDS_];
                float f2 = As[ab + 4];
                float f3 = As[ab + 8 * LDS_ + 4];
                ah[mt][0] = __float_as_uint(f0) & HIMASK;
                ah[mt][1] = __float_as_uint(f1) & HIMASK;
                ah[mt][2] = __float_as_uint(f2) & HIMASK;
                ah[mt][3] = __float_as_uint(f3) & HIMASK;
                al[mt][0] = __float_as_uint(f0 - __uint_as_float(ah[mt][0]));
                al[mt][1] = __float_as_uint(f1 - __uint_as_float(ah[mt][1]));
                al[mt][2] = __float_as_uint(f2 - __uint_as_float(ah[mt][2]));
                al[mt][3] = __float_as_uint(f3 - __uint_as_float(ah[mt][3]));
            }

            // ---- B fragments + MMAs, 4 N-tiles at a time ----
            #pragma unroll
            for (int half = 0; half < 2; ++half) {
                uint32_t bh[4][2], bl[4][2];
                #pragma unroll
                for (int q = 0; q < 4; ++q) {
                    const int nt = half * 4 + q;
                    const int bb = (wn + nt * 8 + grp) * LDS_ + kb + tig;
                    float g0 = Bs[bb];
                    float g1 = Bs[bb + 4];
                    bh[q][0] = __float_as_uint(g0) & HIMASK;
                    bh[q][1] = __float_as_uint(g1) & HIMASK;
                    bl[q][0] = __float_as_uint(g0 - __uint_as_float(bh[q][0]));
                    bl[q][1] = __float_as_uint(g1 - __uint_as_float(bh[q][1]));
                }
                // term-major issue: acc-reuse distance = 8 MMAs
                #pragma unroll
                for (int q = 0; q < 4; ++q)
                    #pragma unroll
                    for (int mt = 0; mt < 2; ++mt)
                        mma_tf32(acc[mt][half * 4 + q], ah[mt], bh[q][0], bh[q][1]);
                #pragma unroll
                for (int q = 0; q < 4; ++q)
                    #pragma unroll
                    for (int mt = 0; mt < 2; ++mt)
                        mma_tf32(acc[mt][half * 4 + q], ah[mt], bl[q][0], bl[q][1]);
                #pragma unroll
                for (int q = 0; q < 4; ++q)
                    #pragma unroll
                    for (int mt = 0; mt < 2; ++mt)
                        mma_tf32(acc[mt][half * 4 + q], al[mt], bh[q][0], bh[q][1]);
            }
        }
        __syncthreads();
    }

    // ---- epilogue: out = a*acc + (1-a)*h ----
    float a = res_alpha[0];
    a = fminf(fmaxf(a, 0.0f), 1.0f);
    const float ra = 1.0f - a;

    #pragma unroll
    for (int mt = 0; mt < 2; ++mt) {
        const int r0 = m0 + wm + mt * 16 + grp;
        #pragma unroll
        for (int nt = 0; nt < 8; ++nt) {
            const int c = n0 + wn + nt * 8 + 2 * tig;
            {
                size_t gi = (size_t)r0 * NDIM + c;
                float2 hv = *reinterpret_cast<const float2*>(&h[gi]);
                float2 o;
                o.x = fmaf(a, acc[mt][nt][0], ra * hv.x);
                o.y = fmaf(a, acc[mt][nt][1], ra * hv.y);
                *reinterpret_cast<float2*>(&out[gi]) = o;
            }
            {
                size_t gi = (size_t)(r0 + 8) * NDIM + c;
                float2 hv = *reinterpret_cast<const float2*>(&h[gi]);
                float2 o;
                o.x = fmaf(a, acc[mt][nt][2], ra * hv.x);
                o.y = fmaf(a, acc[mt][nt][3], ra * hv.y);
                *reinterpret_cast<float2*>(&out[gi]) = o;
            }
        }
    }
}

extern "C" void kernel_launch(void* const* d_in, const int* in_sizes, int n_in,
                              void* d_out, int out_size) {
    const float* h         = (const float*)d_in[0];   // [8, 2048, 256]
    // d_in[1] = adj (unused)
    const float* W         = (const float*)d_in[2];   // [4, 256, 64]
    const float* res_alpha = (const float*)d_in[3];
    float* out             = (float*)d_out;

    const int M = in_sizes[0] / K_DIM;                // 16384

    prep_Bt<<<(NDIM * K_DIM) / 256, 256>>>(W);

    const int smem_bytes = 2 * STAGEF * 4;            // 73728
    cudaFuncSetAttribute(gat_mma_gemm,
                         cudaFuncAttributeMaxDynamicSharedMemorySize, smem_bytes);
    dim3 grid(NDIM / BN, M / BM);                     // (2, 128)
    gat_mma_gemm<<<grid, THREADS, smem_bytes>>>(h, res_alpha, out);
}

// round 7
// speedup vs baseline: 1.2850x; 1.2850x over previous
#include <cuda_runtime.h>
#include <cstdint>

// out[m,n] = a * (h[m,:] @ B2[:,n]) + (1-a) * h[m,n]
// B2[k, head*64+d] = W[head,k,d]; a = clip(res_alpha,0,1).
// (softmax row-sums are exactly 1 -> attention block is identity; adj unused)
//
// R7: bf16 2-split x 3-term emulated-fp32 GEMM on mma.m16n8k16:
//   x = hi + lo, hi = top 16 bits of fp32 (exact bf16), lo = bf16(x - hi)
//   D = Ahi*Bhi + Ahi*Blo + Alo*Bhi   (dropped terms ~2^-16 relative)
// Halves the MMA instruction count vs 3xTF32 m16n8k8 (2048 MAC/instr).
// B pre-split+packed to bf16x2 by prep kernel (no B split ALU in mainloop).

#define K_DIM   256
#define NDIM    256
#define BM      128
#define BN      128
#define KC      32
#define NCHUNK  (K_DIM / KC)
#define A_LDS   36                      // A smem row stride in floats
#define B_LDS   20                      // B smem row stride in uint32 (16 data + 4 pad)
#define A_STF   (BM * A_LDS)            // 4608 floats  = 18432 B
#define B_STU   (BN * B_LDS)            // 2560 uint32  = 10240 B
#define STAGE_B (A_STF * 4 + 2 * B_STU * 4)   // 38912 bytes per stage
#define THREADS 256

__device__ uint32_t g_Bh[NDIM * K_DIM / 2];   // [n][k/2] bf16x2 hi
__device__ uint32_t g_Bl[NDIM * K_DIM / 2];   // [n][k/2] bf16x2 lo

// ---- pack two fp32 into bf16x2 (hi) and residual bf16x2 (lo), truncation ----
__device__ __forceinline__ void split_pack(float f0, float f1,
                                           uint32_t& hi, uint32_t& lo) {
    uint32_t u0 = __float_as_uint(f0);
    uint32_t u1 = __float_as_uint(f1);
    hi = __byte_perm(u0, u1, 0x7632);
    float r0 = f0 - __uint_as_float(u0 & 0xFFFF0000u);
    float r1 = f1 - __uint_as_float(u1 & 0xFFFF0000u);
    lo = __byte_perm(__float_as_uint(r0), __float_as_uint(r1), 0x7632);
}

// ---- prep: transpose W -> [n][k], split to bf16x2 hi/lo pairs ----
__global__ void prep_Bt(const float* __restrict__ W) {
    int idx = blockIdx.x * blockDim.x + threadIdx.x;   // 32768
    int n = idx >> 7;                 // 0..255
    int p = idx & 127;                // k-pair 0..127
    int k0 = p << 1;
    int head = n >> 6, d = n & 63;
    float f0 = W[((size_t)head * K_DIM + k0) * 64 + d];
    float f1 = W[((size_t)head * K_DIM + k0 + 1) * 64 + d];
    uint32_t hi, lo;
    split_pack(f0, f1, hi, lo);
    g_Bh[n * 128 + p] = hi;
    g_Bl[n * 128 + p] = lo;
}

__device__ __forceinline__ void mma_bf16(float d[4],
                                         const uint32_t a[4],
                                         uint32_t b0, uint32_t b1) {
    asm volatile(
        "mma.sync.aligned.m16n8k16.row.col.f32.bf16.bf16.f32 "
        "{%0,%1,%2,%3}, {%4,%5,%6,%7}, {%8,%9}, {%0,%1,%2,%3};"
        : "+f"(d[0]), "+f"(d[1]), "+f"(d[2]), "+f"(d[3])
        : "r"(a[0]), "r"(a[1]), "r"(a[2]), "r"(a[3]), "r"(b0), "r"(b1));
}

__device__ __forceinline__ void cp16(uint32_t saddr, const void* g) {
    asm volatile("cp.async.cg.shared.global [%0], [%1], 16;"
                 :: "r"(saddr), "l"(g) : "memory");
}

__global__ __launch_bounds__(THREADS, 2)
void gat_mma_gemm(const float* __restrict__ h,
                  const float* __restrict__ res_alpha,
                  float* __restrict__ out)
{
    extern __shared__ float smem[];

    const int tid = threadIdx.x;
    const int wid = tid >> 5;
    const int lid = tid & 31;
    const int grp = lid >> 2;          // 0..7
    const int tig = lid & 3;           // 0..3

    const int m0 = blockIdx.y * BM;
    const int n0 = blockIdx.x * BN;
    const int wm = (wid & 3) * 32;     // warp M offset
    const int wn = (wid >> 2) * 64;    // warp N offset

    const uint32_t smem_b = (uint32_t)__cvta_generic_to_shared(smem);

    float acc[2][8][4];
    #pragma unroll
    for (int mt = 0; mt < 2; ++mt)
        #pragma unroll
        for (int nt = 0; nt < 8; ++nt)
            #pragma unroll
            for (int q = 0; q < 4; ++q)
                acc[mt][nt][q] = 0.0f;

    // ---- async load of chunk c into stage s ----
    auto load_chunk = [&](int c, int s) {
        const int k0 = c * KC;
        const uint32_t sa  = smem_b + (uint32_t)(s * STAGE_B);
        const uint32_t sbh = sa + A_STF * 4u;
        const uint32_t sbl = sbh + B_STU * 4u;
        // A: 128 rows x 32 fp32 = 1024 x 16B
        #pragma unroll
        for (int j = 0; j < 4; ++j) {
            int fid = tid + j * THREADS;
            int row = fid >> 3;
            int kq = (fid & 7) << 2;
            cp16(sa + (uint32_t)(row * A_LDS + kq) * 4u,
                 &h[(size_t)(m0 + row) * K_DIM + k0 + kq]);
        }
        // B hi/lo: 128 rows x 16 u32 = 512 x 16B each
        #pragma unroll
        for (int j = 0; j < 2; ++j) {
            int fid = tid + j * THREADS;
            int row = fid >> 2;
            int p4 = (fid & 3) << 2;
            int gidx = (n0 + row) * 128 + c * 16 + p4;
            cp16(sbh + (uint32_t)(row * B_LDS + p4) * 4u, &g_Bh[gidx]);
            cp16(sbl + (uint32_t)(row * B_LDS + p4) * 4u, &g_Bl[gidx]);
        }
        asm volatile("cp.async.commit_group;" ::: "memory");
    };

    load_chunk(0, 0);

    for (int c = 0; c < NCHUNK; ++c) {
        const int s = c & 1;
        if (c + 1 < NCHUNK) {
            load_chunk(c + 1, (c + 1) & 1);
            asm volatile("cp.async.wait_group 1;" ::: "memory");
        } else {
            asm volatile("cp.async.wait_group 0;" ::: "memory");
        }
        __syncthreads();

        const float*    As  = smem + s * (STAGE_B / 4);
        const uint32_t* Bsh = (const uint32_t*)(As + A_STF);
        const uint32_t* Bsl = Bsh + B_STU;

        #pragma unroll
        for (int k16 = 0; k16 < KC / 16; ++k16) {
            const int kb = k16 * 16;        // k offset in floats
            const int pb = k16 * 8;         // k-pair offset in u32

            // ---- A fragments (both M tiles), split+pack in regs ----
            uint32_t ah[2][4], al[2][4];
            #pragma unroll
            for (int mt = 0; mt < 2; ++mt) {
                const int r0 = (wm + mt * 16 + grp) * A_LDS;
                const int r1 = r0 + 8 * A_LDS;
                float2 v0 = *reinterpret_cast<const float2*>(&As[r0 + kb + 2 * tig]);
                float2 v1 = *reinterpret_cast<const float2*>(&As[r1 + kb + 2 * tig]);
                float2 v2 = *reinterpret_cast<const float2*>(&As[r0 + kb + 2 * tig + 8]);
                float2 v3 = *reinterpret_cast<const float2*>(&As[r1 + kb + 2 * tig + 8]);
                split_pack(v0.x, v0.y, ah[mt][0], al[mt][0]);
                split_pack(v1.x, v1.y, ah[mt][1], al[mt][1]);
                split_pack(v2.x, v2.y, ah[mt][2], al[mt][2]);
                split_pack(v3.x, v3.y, ah[mt][3], al[mt][3]);
            }

            // ---- B fragments + MMAs, 4 N-tiles per half ----
            #pragma unroll
            for (int half = 0; half < 2; ++half) {
                uint32_t bh[4][2], bl[4][2];
                #pragma unroll
                for (int q = 0; q < 4; ++q) {
                    const int nb = (wn + (half * 4 + q) * 8 + grp) * B_LDS + pb;
                    bh[q][0] = Bsh[nb + tig];
                    bh[q][1] = Bsh[nb + tig + 4];
                    bl[q][0] = Bsl[nb + tig];
                    bl[q][1] = Bsl[nb + tig + 4];
                }
                // term-major: acc-reuse distance = 8 MMAs
                #pragma unroll
                for (int q = 0; q < 4; ++q)
                    #pragma unroll
                    for (int mt = 0; mt < 2; ++mt)
                        mma_bf16(acc[mt][half * 4 + q], ah[mt], bh[q][0], bh[q][1]);
                #pragma unroll
                for (int q = 0; q < 4; ++q)
                    #pragma unroll
                    for (int mt = 0; mt < 2; ++mt)
                        mma_bf16(acc[mt][half * 4 + q], ah[mt], bl[q][0], bl[q][1]);
                #pragma unroll
                for (int q = 0; q < 4; ++q)
                    #pragma unroll
                    for (int mt = 0; mt < 2; ++mt)
                        mma_bf16(acc[mt][half * 4 + q], al[mt], bh[q][0], bh[q][1]);
            }
        }
        __syncthreads();
    }

    // ---- epilogue: out = a*acc + (1-a)*h ----
    float a = res_alpha[0];
    a = fminf(fmaxf(a, 0.0f), 1.0f);
    const float ra = 1.0f - a;

    #pragma unroll
    for (int mt = 0; mt < 2; ++mt) {
        const int r0 = m0 + wm + mt * 16 + grp;
        #pragma unroll
        for (int nt = 0; nt < 8; ++nt) {
            const int cc = n0 + wn + nt * 8 + 2 * tig;
            {
                size_t gi = (size_t)r0 * NDIM + cc;
                float2 hv = *reinterpret_cast<const float2*>(&h[gi]);
                float2 o;
                o.x = fmaf(a, acc[mt][nt][0], ra * hv.x);
                o.y = fmaf(a, acc[mt][nt][1], ra * hv.y);
                *reinterpret_cast<float2*>(&out[gi]) = o;
            }
            {
                size_t gi = (size_t)(r0 + 8) * NDIM + cc;
                float2 hv = *reinterpret_cast<const float2*>(&h[gi]);
                float2 o;
                o.x = fmaf(a, acc[mt][nt][2], ra * hv.x);
                o.y = fmaf(a, acc[mt][nt][3], ra * hv.y);
                *reinterpret_cast<float2*>(&out[gi]) = o;
            }
        }
    }
}

extern "C" void kernel_launch(void* const* d_in, const int* in_sizes, int n_in,
                              void* d_out, int out_size) {
    const float* h         = (const float*)d_in[0];   // [8, 2048, 256]
    // d_in[1] = adj (unused)
    const float* W         = (const float*)d_in[2];   // [4, 256, 64]
    const float* res_alpha = (const float*)d_in[3];
    float* out             = (float*)d_out;

    const int M = in_sizes[0] / K_DIM;                // 16384

    prep_Bt<<<(NDIM * K_DIM / 2) / 256, 256>>>(W);

    const int smem_bytes = 2 * STAGE_B;               // 77824
    cudaFuncSetAttribute(gat_mma_gemm,
                         cudaFuncAttributeMaxDynamicSharedMemorySize, smem_bytes);
    dim3 grid(NDIM / BN, M / BM);                     // (2, 128)
    gat_mma_gemm<<<grid, THREADS, smem_bytes>>>(h, res_alpha, out);
}